// round 14
// baseline (speedup 1.0000x reference)
#include <cuda_runtime.h>
#include <cuda_fp16.h>
#include <math.h>
#include <stdint.h>

#define Bb 8
#define Nn 4096
#define Dd 256
#define Hh 256

// ---------------- static device scratch (allocation-free) ----------------
__device__ __half  g_xh[(size_t)Bb * Nn * Dd];           // 16.8 MB  x in fp16
__device__ uint8_t g_Q8[(size_t)Bb * Nn * Hh];           // 8.4 MB   Q in e4m3
__device__ uint8_t g_K8[(size_t)Bb * Nn * Hh];           // 8.4 MB   K in e4m3
__device__ float   g_V[(size_t)Bb * Nn * Hh];            // 33.5 MB  V fp32
__device__ __half  g_P[(size_t)Bb * Nn * Nn];            // 268 MB: P = exp(S) fp16
__device__ __half  g_Wth[3 * Dd * Hh];                   // W^T fp16 for Q,K,V
__device__ float   g_z[Bb * Nn];                         // row sums Z
__device__ float   g_w[Bb * Nn];                         // column weights

// ================= helpers =================
__device__ __forceinline__ uint32_t smem_u32(const void* p) {
    uint32_t a;
    asm("{ .reg .u64 t; cvta.to.shared.u64 t, %1; cvt.u32.u64 %0, t; }" : "=r"(a) : "l"(p));
    return a;
}
__device__ __forceinline__ void cpasync16(uint32_t dst, const void* src) {
    asm volatile("cp.async.ca.shared.global [%0], [%1], 16;" :: "r"(dst), "l"(src));
}
#define CP_COMMIT() asm volatile("cp.async.commit_group;" ::: "memory")
#define CP_WAIT(N)  asm volatile("cp.async.wait_group %0;" :: "n"(N) : "memory")

__device__ __forceinline__ void ldm_x4(uint32_t& r0, uint32_t& r1, uint32_t& r2, uint32_t& r3,
                                       uint32_t addr) {
    asm volatile("ldmatrix.sync.aligned.m8n8.x4.shared.b16 {%0,%1,%2,%3}, [%4];"
                 : "=r"(r0), "=r"(r1), "=r"(r2), "=r"(r3) : "r"(addr));
}
// fp16 inputs, fp32 accumulate (QKV projection)
__device__ __forceinline__ void mma_f16f32(float* c,
                                           uint32_t a0, uint32_t a1, uint32_t a2, uint32_t a3,
                                           uint32_t b0, uint32_t b1) {
    asm volatile(
        "mma.sync.aligned.m16n8k16.row.col.f32.f16.f16.f32 "
        "{%0,%1,%2,%3}, {%4,%5,%6,%7}, {%8,%9}, {%0,%1,%2,%3};"
        : "+f"(c[0]), "+f"(c[1]), "+f"(c[2]), "+f"(c[3])
        : "r"(a0), "r"(a1), "r"(a2), "r"(a3), "r"(b0), "r"(b1));
}
// e4m3 inputs, fp32 accumulate (scores)
__device__ __forceinline__ void mma_fp8(float* c,
                                        uint32_t a0, uint32_t a1, uint32_t a2, uint32_t a3,
                                        uint32_t b0, uint32_t b1) {
    asm volatile(
        "mma.sync.aligned.m16n8k32.row.col.f32.e4m3.e4m3.f32 "
        "{%0,%1,%2,%3}, {%4,%5,%6,%7}, {%8,%9}, {%0,%1,%2,%3};"
        : "+f"(c[0]), "+f"(c[1]), "+f"(c[2]), "+f"(c[3])
        : "r"(a0), "r"(a1), "r"(a2), "r"(a3), "r"(b0), "r"(b1));
}
__device__ __forceinline__ uint16_t pack_e4m3x2(float lo, float hi) {
    uint16_t u;
    asm("cvt.rn.satfinite.e4m3x2.f32 %0, %1, %2;" : "=h"(u) : "f"(hi), "f"(lo));
    return u;
}
#define SW128(o) ((o) ^ (((o) >> 3) & 0x70u))

#define QKV_DYN_SMEM 65536    // 2 buffers x (A 16KB + B 16KB)
#define SC_DYN_SMEM  65536    // 2 buffers x (A 16KB + B 16KB), fp8

// ---------------- kernel 0: x -> fp16 (+ zero accumulators) ----------------
__global__ __launch_bounds__(256) void convert_x_kernel(const float* __restrict__ x,
                                                        float* __restrict__ out) {
    int i = blockIdx.x * 256 + threadIdx.x;           // one float2 -> half2
    float2 v = reinterpret_cast<const float2*>(x)[i];
    reinterpret_cast<__half2*>(g_xh)[i] = __floats2half2_rn(v.x, v.y);
    if (i < Bb * Nn) { g_w[i] = 0.0f; g_z[i] = 0.0f; }
    if (i < Bb * Hh) out[i] = 0.0f;
}

// ---------------- kernel 1: W transpose -> fp16 ----------------
__global__ void transpose_w_kernel(const float* __restrict__ Wq,
                                   const float* __restrict__ Wk,
                                   const float* __restrict__ Wv) {
    const float* W = (blockIdx.z == 0) ? Wq : (blockIdx.z == 1) ? Wk : Wv;
    __half* Wt = g_Wth + blockIdx.z * (Dd * Hh);
    __shared__ float t[32][33];
    const int x0 = blockIdx.x * 32, y0 = blockIdx.y * 32;
    #pragma unroll
    for (int i = threadIdx.y; i < 32; i += 8)
        t[i][threadIdx.x] = W[(size_t)(y0 + i) * Hh + x0 + threadIdx.x];
    __syncthreads();
    #pragma unroll
    for (int i = threadIdx.y; i < 32; i += 8)
        Wt[(size_t)(x0 + i) * Dd + y0 + threadIdx.x] = __float2half(t[threadIdx.x][i]);
}

// ---------------- kernel 2: QKV projection, fp16 inputs / f32 acc ----------------
// CTA tile 128(r) x 128(h), K=256 in 4 chunks of k64. Warp tile 64x32. ldmatrix loads.
// Q,K written e4m3; V fp32.  grid: (Hh/128, (B*N)/128, 3)  block: 256
__global__ __launch_bounds__(256, 2) void qkv_mma_kernel(
    const float* __restrict__ bq, const float* __restrict__ bk, const float* __restrict__ bv)
{
    extern __shared__ float dynsm[];
    const uint32_t sb = smem_u32(dynsm);
    const int tid  = threadIdx.x;
    const int wid  = tid >> 5;
    const int lane = tid & 31;
    const int g = lane >> 2, t = lane & 3;
    const int wm = (wid & 1) * 64;
    const int wn = (wid >> 1) * 32;
    const int lr = tid >> 3;
    const int lc = tid & 7;

    const int z  = blockIdx.z;
    const float* bias = (z == 0) ? bq : (z == 1) ? bk : bv;
    const int r0 = blockIdx.y * 128;
    const int h0 = blockIdx.x * 128;

    const uint32_t stsOff = SW128((uint32_t)(lr * 128 + lc * 16));
    const __half* Aq = g_xh + (size_t)r0 * Dd + (size_t)lr * 256 + lc * 8;
    const __half* Bk = g_Wth + z * (Dd * Hh) + (size_t)h0 * Dd + (size_t)lr * 256 + lc * 8;

    const int quad = lane >> 3, rr = lane & 7;
    const uint32_t swzL = (uint32_t)rr << 4;
    const uint32_t aRowOff = (uint32_t)(wm + (quad & 1) * 8 + rr) * 128u;
    const uint32_t colSelA = (uint32_t)(quad >> 1) * 16u;
    const uint32_t bRowOff = (uint32_t)(wn + (quad >> 1) * 8 + rr) * 128u;
    const uint32_t colSelB = (uint32_t)(quad & 1) * 16u;

    float c[4][4][4];
    #pragma unroll
    for (int mt = 0; mt < 4; mt++)
        #pragma unroll
        for (int nt = 0; nt < 4; nt++)
            #pragma unroll
            for (int r = 0; r < 4; r++) c[mt][nt][r] = 0.0f;

    auto issue = [&](int ch, int buf) {
        const uint32_t ba = sb + (uint32_t)buf * 32768u;
        const __half* qa = Aq + ch * 64;
        const __half* ka = Bk + ch * 64;
        #pragma unroll
        for (int i = 0; i < 4; i++) {
            cpasync16(ba + stsOff + i * 4096u,          qa + (size_t)i * 32 * 256);
            cpasync16(ba + 16384u + stsOff + i * 4096u, ka + (size_t)i * 32 * 256);
        }
        CP_COMMIT();
    };
    auto compute = [&](int buf) {
        const uint32_t aB = sb + (uint32_t)buf * 32768u + aRowOff;
        const uint32_t bB = sb + (uint32_t)buf * 32768u + 16384u + bRowOff;
        #pragma unroll
        for (int ks = 0; ks < 4; ks++) {
            const uint32_t ctA = ((uint32_t)(ks * 32) + colSelA) ^ swzL;
            const uint32_t ctB = ((uint32_t)(ks * 32) + colSelB) ^ swzL;
            uint32_t b[4][2];
            #pragma unroll
            for (int np = 0; np < 2; np++)
                ldm_x4(b[2*np][0], b[2*np][1], b[2*np+1][0], b[2*np+1][1],
                       bB + np * 2048u + ctB);
            #pragma unroll
            for (int mt = 0; mt < 4; mt++) {
                uint32_t a0, a1, a2, a3;
                ldm_x4(a0, a1, a2, a3, aB + mt * 2048u + ctA);
                #pragma unroll
                for (int nt = 0; nt < 4; nt++)
                    mma_f16f32(c[mt][nt], a0, a1, a2, a3, b[nt][0], b[nt][1]);
            }
        }
    };

    issue(0, 0); issue(1, 1);
    #pragma unroll 1
    for (int ch = 0; ch < 4; ch++) {
        if (ch == 3) { CP_WAIT(0); } else { CP_WAIT(1); }
        __syncthreads();
        compute(ch & 1);
        __syncthreads();
        if (ch + 2 < 4) issue(ch + 2, ch & 1);
    }

    if (z == 2) {
        #pragma unroll
        for (int mt = 0; mt < 4; mt++) {
            const int row = r0 + wm + mt * 16 + g;
            #pragma unroll
            for (int nt = 0; nt < 4; nt++) {
                const int col = h0 + wn + nt * 8 + 2 * t;
                float2 bc = *reinterpret_cast<const float2*>(&bias[col]);
                float2 v0, v1;
                v0.x = c[mt][nt][0] + bc.x; v0.y = c[mt][nt][1] + bc.y;
                v1.x = c[mt][nt][2] + bc.x; v1.y = c[mt][nt][3] + bc.y;
                *reinterpret_cast<float2*>(&g_V[(size_t)row       * Hh + col]) = v0;
                *reinterpret_cast<float2*>(&g_V[(size_t)(row + 8) * Hh + col]) = v1;
            }
        }
    } else {
        uint8_t* out8 = (z == 0) ? g_Q8 : g_K8;
        #pragma unroll
        for (int mt = 0; mt < 4; mt++) {
            const int row = r0 + wm + mt * 16 + g;
            #pragma unroll
            for (int nt = 0; nt < 4; nt++) {
                const int col = h0 + wn + nt * 8 + 2 * t;
                float2 bc = *reinterpret_cast<const float2*>(&bias[col]);
                *reinterpret_cast<uint16_t*>(&out8[(size_t)row       * Hh + col]) =
                    pack_e4m3x2(c[mt][nt][0] + bc.x, c[mt][nt][1] + bc.y);
                *reinterpret_cast<uint16_t*>(&out8[(size_t)(row + 8) * Hh + col]) =
                    pack_e4m3x2(c[mt][nt][2] + bc.x, c[mt][nt][3] + bc.y);
            }
        }
    }
}

// ---------------- kernel 3: P = exp(Q K^T * scale), Z row-sums (fp8 MMA) ----------------
// e4m3 in, f32 acc. CTA tile 128(q) x 128(k); warp tile 64x32; ldmatrix loads.
// K=256 in 2 chunks of 128 bytes (4 x k32 steps each).
// grid: (N/128, N/128, B)  block: 256
__global__ __launch_bounds__(256, 2) void scores_fused_kernel() {
    extern __shared__ float dynsm[];
    __shared__ float rsum[128];
    const uint32_t sb = smem_u32(dynsm);
    const int tid  = threadIdx.x;
    const int wid  = tid >> 5;
    const int lane = tid & 31;
    const int g = lane >> 2, t = lane & 3;
    const int wm = (wid & 1) * 64;
    const int wn = (wid >> 1) * 32;
    const int lr = tid >> 3;
    const int lc = tid & 7;

    const int b  = blockIdx.z;
    const int q0 = blockIdx.y * 128;
    const int k0 = blockIdx.x * 128;

    const uint32_t stsOff = SW128((uint32_t)(lr * 128 + lc * 16));
    const uint8_t* Aq = g_Q8 + (size_t)(b * Nn + q0) * Hh + (size_t)lr * 256 + lc * 16;
    const uint8_t* Bk = g_K8 + (size_t)(b * Nn + k0) * Hh + (size_t)lr * 256 + lc * 16;

    const int quad = lane >> 3, rr = lane & 7;
    const uint32_t swzL = (uint32_t)rr << 4;
    const uint32_t aRowOff = (uint32_t)(wm + (quad & 1) * 8 + rr) * 128u;
    const uint32_t colSelA = (uint32_t)(quad >> 1) * 16u;
    const uint32_t bRowOff = (uint32_t)(wn + (quad >> 1) * 8 + rr) * 128u;
    const uint32_t colSelB = (uint32_t)(quad & 1) * 16u;

    float c[4][4][4];   // f32 accumulators: 64 regs
    #pragma unroll
    for (int mt = 0; mt < 4; mt++)
        #pragma unroll
        for (int nt = 0; nt < 4; nt++)
            #pragma unroll
            for (int r = 0; r < 4; r++) c[mt][nt][r] = 0.0f;

    auto issue = [&](int ch, int buf) {
        const uint32_t ba = sb + (uint32_t)buf * 32768u;
        const uint8_t* qa = Aq + ch * 128;
        const uint8_t* ka = Bk + ch * 128;
        #pragma unroll
        for (int i = 0; i < 4; i++) {
            cpasync16(ba + stsOff + i * 4096u,          qa + (size_t)i * 32 * 256);
            cpasync16(ba + 16384u + stsOff + i * 4096u, ka + (size_t)i * 32 * 256);
        }
        CP_COMMIT();
    };
    auto compute = [&](int buf) {
        const uint32_t aB = sb + (uint32_t)buf * 32768u + aRowOff;
        const uint32_t bB = sb + (uint32_t)buf * 32768u + 16384u + bRowOff;
        #pragma unroll
        for (int ks = 0; ks < 4; ks++) {      // 4 x k32 steps (32 bytes each)
            const uint32_t ctA = ((uint32_t)(ks * 32) + colSelA) ^ swzL;
            const uint32_t ctB = ((uint32_t)(ks * 32) + colSelB) ^ swzL;
            uint32_t b[4][2];
            #pragma unroll
            for (int np = 0; np < 2; np++)
                ldm_x4(b[2*np][0], b[2*np][1], b[2*np+1][0], b[2*np+1][1],
                       bB + np * 2048u + ctB);
            #pragma unroll
            for (int mt = 0; mt < 4; mt++) {
                uint32_t a0, a1, a2, a3;
                ldm_x4(a0, a1, a2, a3, aB + mt * 2048u + ctA);
                #pragma unroll
                for (int nt = 0; nt < 4; nt++)
                    mma_fp8(c[mt][nt], a0, a1, a2, a3, b[nt][0], b[nt][1]);
            }
        }
    };

    issue(0, 0); issue(1, 1);
    #pragma unroll 1
    for (int ch = 0; ch < 2; ch++) {
        if (ch == 1) { CP_WAIT(0); } else { CP_WAIT(1); }
        __syncthreads();
        compute(ch & 1);
        __syncthreads();
    }

    // ---- fused epilogue: exp, fp16 store, per-row Z partial sums ----
    if (tid < 128) rsum[tid] = 0.0f;
    __syncthreads();

    const float scale = 0.0625f;    // 1/sqrt(256)
    __half* Ph = g_P + (size_t)(b * Nn) * Nn;

    #pragma unroll
    for (int mt = 0; mt < 4; mt++) {
        const int row = wm + mt * 16 + g;
        float s0 = 0.0f, s1 = 0.0f;
        #pragma unroll
        for (int nt = 0; nt < 4; nt++) {
            const int col = k0 + wn + nt * 8 + 2 * t;
            float e0 = __expf(c[mt][nt][0] * scale);
            float e1 = __expf(c[mt][nt][1] * scale);
            float e2 = __expf(c[mt][nt][2] * scale);
            float e3 = __expf(c[mt][nt][3] * scale);
            s0 += e0 + e1;
            s1 += e2 + e3;
            *reinterpret_cast<__half2*>(&Ph[(size_t)(q0 + row)     * Nn + col]) =
                __floats2half2_rn(e0, e1);
            *reinterpret_cast<__half2*>(&Ph[(size_t)(q0 + row + 8) * Nn + col]) =
                __floats2half2_rn(e2, e3);
        }
        s0 += __shfl_xor_sync(0xFFFFFFFFu, s0, 1);
        s0 += __shfl_xor_sync(0xFFFFFFFFu, s0, 2);
        s1 += __shfl_xor_sync(0xFFFFFFFFu, s1, 1);
        s1 += __shfl_xor_sync(0xFFFFFFFFu, s1, 2);
        if (t == 0) {
            atomicAdd(&rsum[row],     s0);
            atomicAdd(&rsum[row + 8], s1);
        }
    }
    __syncthreads();
    if (tid < 128) atomicAdd(&g_z[b * Nn + q0 + tid], rsum[tid]);
}

// ---------------- kernel 4: w[b,k] = sum_q P[q,k] / Z[q]  (invZ fused) ----------------
__global__ __launch_bounds__(128) void colsum_kernel() {
    const int b  = blockIdx.z;
    const int k2 = blockIdx.x * 128 + threadIdx.x;
    const int q0 = blockIdx.y * 256;

    __shared__ float iz[256];
    if (threadIdx.x < 128) {
        iz[threadIdx.x]       = 1.0f / g_z[b * Nn + q0 + threadIdx.x];
        iz[threadIdx.x + 128] = 1.0f / g_z[b * Nn + q0 + 128 + threadIdx.x];
    }
    __syncthreads();

    const __half2* Pb = reinterpret_cast<const __half2*>(g_P + (size_t)(b * Nn) * Nn);

    float ax = 0.0f, ay = 0.0f;
    #pragma unroll 4
    for (int q = 0; q < 256; q++) {
        float2 v = __half22float2(Pb[(size_t)(q0 + q) * (Nn / 2) + k2]);
        float w = iz[q];
        ax += v.x * w;
        ay += v.y * w;
    }
    atomicAdd(&g_w[b * Nn + 2 * k2],     ax);
    atomicAdd(&g_w[b * Nn + 2 * k2 + 1], ay);
}

// ---------------- kernel 5: out[b,h] = (1/N) sum_k w[b,k] V[b,k,h] ----------------
__global__ __launch_bounds__(256) void out_kernel(float* __restrict__ out) {
    const int b  = blockIdx.x;
    const int ks = blockIdx.y;
    const int h  = threadIdx.x;
    const float* Vb = g_V + (size_t)b * Nn * Hh;

    float acc = 0.0f;
    #pragma unroll 8
    for (int k = ks * 256; k < ks * 256 + 256; k++)
        acc += g_w[b * Nn + k] * Vb[(size_t)k * Hh + h];

    atomicAdd(&out[b * Hh + h], acc * (1.0f / Nn));
}

// ---------------- launch ----------------
extern "C" void kernel_launch(void* const* d_in, const int* in_sizes, int n_in,
                              void* d_out, int out_size) {
    const float* x  = (const float*)d_in[0];
    const float* Wq = (const float*)d_in[1];
    const float* bq = (const float*)d_in[2];
    const float* Wk = (const float*)d_in[3];
    const float* bk = (const float*)d_in[4];
    const float* Wv = (const float*)d_in[5];
    const float* bv = (const float*)d_in[6];
    float* out = (float*)d_out;

    cudaFuncSetAttribute(qkv_mma_kernel,
                         cudaFuncAttributeMaxDynamicSharedMemorySize, QKV_DYN_SMEM);
    cudaFuncSetAttribute(scores_fused_kernel,
                         cudaFuncAttributeMaxDynamicSharedMemorySize, SC_DYN_SMEM);

    convert_x_kernel<<<(Bb * Nn * Dd / 2) / 256, 256>>>(x, out);
    transpose_w_kernel<<<dim3(8, 8, 3), dim3(32, 8)>>>(Wq, Wk, Wv);
    qkv_mma_kernel<<<dim3(Hh / 128, (Bb * Nn) / 128, 3), 256, QKV_DYN_SMEM>>>(bq, bk, bv);
    scores_fused_kernel<<<dim3(Nn / 128, Nn / 128, Bb), 256, SC_DYN_SMEM>>>();
    colsum_kernel<<<dim3(Nn / 256, Nn / 256, Bb), 128>>>();
    out_kernel<<<dim3(Bb, 16), 256>>>(out);
}

// round 15
// speedup vs baseline: 1.0333x; 1.0333x over previous
#include <cuda_runtime.h>
#include <cuda_fp16.h>
#include <math.h>
#include <stdint.h>

#define Bb 8
#define Nn 4096
#define Dd 256
#define Hh 256

// ---------------- static device scratch (allocation-free) ----------------
__device__ __half g_xh[(size_t)Bb * Nn * Dd];            // 16.8 MB  x in fp16
__device__ __half g_Qh[(size_t)Bb * Nn * Hh];            // 16.8 MB  Q in fp16
__device__ __half g_Kh[(size_t)Bb * Nn * Hh];            // 16.8 MB  K in fp16
__device__ float  g_V[(size_t)Bb * Nn * Hh];             // 33.5 MB  V fp32
__device__ __half g_P[(size_t)Bb * Nn * Nn];             // 268 MB: P = exp(S) fp16
__device__ __half g_Wth[3 * Dd * Hh];                    // W^T fp16 for Q,K,V
__device__ float  g_z[Bb * Nn];                          // row sums Z
__device__ float  g_w[Bb * Nn];                          // column weights

// ================= helpers =================
__device__ __forceinline__ uint32_t smem_u32(const void* p) {
    uint32_t a;
    asm("{ .reg .u64 t; cvta.to.shared.u64 t, %1; cvt.u32.u64 %0, t; }" : "=r"(a) : "l"(p));
    return a;
}
__device__ __forceinline__ void cpasync16(uint32_t dst, const void* src) {
    asm volatile("cp.async.ca.shared.global [%0], [%1], 16;" :: "r"(dst), "l"(src));
}
#define CP_COMMIT() asm volatile("cp.async.commit_group;" ::: "memory")
#define CP_WAIT(N)  asm volatile("cp.async.wait_group %0;" :: "n"(N) : "memory")

__device__ __forceinline__ void ldm_x4(uint32_t& r0, uint32_t& r1, uint32_t& r2, uint32_t& r3,
                                       uint32_t addr) {
    asm volatile("ldmatrix.sync.aligned.m8n8.x4.shared.b16 {%0,%1,%2,%3}, [%4];"
                 : "=r"(r0), "=r"(r1), "=r"(r2), "=r"(r3) : "r"(addr));
}
// fp16 inputs, fp32 accumulate (QKV projection)
__device__ __forceinline__ void mma_f16f32(float* c,
                                           uint32_t a0, uint32_t a1, uint32_t a2, uint32_t a3,
                                           uint32_t b0, uint32_t b1) {
    asm volatile(
        "mma.sync.aligned.m16n8k16.row.col.f32.f16.f16.f32 "
        "{%0,%1,%2,%3}, {%4,%5,%6,%7}, {%8,%9}, {%0,%1,%2,%3};"
        : "+f"(c[0]), "+f"(c[1]), "+f"(c[2]), "+f"(c[3])
        : "r"(a0), "r"(a1), "r"(a2), "r"(a3), "r"(b0), "r"(b1));
}
// fp16 inputs, fp16 accumulate (scores)
__device__ __forceinline__ void mma_f16(uint32_t* c,
                                        uint32_t a0, uint32_t a1, uint32_t a2, uint32_t a3,
                                        uint32_t b0, uint32_t b1) {
    asm volatile(
        "mma.sync.aligned.m16n8k16.row.col.f16.f16.f16.f16 "
        "{%0,%1}, {%2,%3,%4,%5}, {%6,%7}, {%0,%1};"
        : "+r"(c[0]), "+r"(c[1])
        : "r"(a0), "r"(a1), "r"(a2), "r"(a3), "r"(b0), "r"(b1));
}
#define SW128(o) ((o) ^ (((o) >> 3) & 0x70u))

#define QKV_DYN_SMEM 65536    // 2 buffers x (A 16KB + B 16KB)
#define SC_DYN_SMEM  98304    // 2 buffers x (A 16KB + B 32KB)

// ---------------- kernel 0: x -> fp16 (+ zero accumulators) ----------------
__global__ __launch_bounds__(256) void convert_x_kernel(const float* __restrict__ x,
                                                        float* __restrict__ out) {
    int i = blockIdx.x * 256 + threadIdx.x;           // one float2 -> half2
    float2 v = reinterpret_cast<const float2*>(x)[i];
    reinterpret_cast<__half2*>(g_xh)[i] = __floats2half2_rn(v.x, v.y);
    if (i < Bb * Nn) { g_w[i] = 0.0f; g_z[i] = 0.0f; }
    if (i < Bb * Hh) out[i] = 0.0f;
}

// ---------------- kernel 1: W transpose -> fp16 ----------------
__global__ void transpose_w_kernel(const float* __restrict__ Wq,
                                   const float* __restrict__ Wk,
                                   const float* __restrict__ Wv) {
    const float* W = (blockIdx.z == 0) ? Wq : (blockIdx.z == 1) ? Wk : Wv;
    __half* Wt = g_Wth + blockIdx.z * (Dd * Hh);
    __shared__ float t[32][33];
    const int x0 = blockIdx.x * 32, y0 = blockIdx.y * 32;
    #pragma unroll
    for (int i = threadIdx.y; i < 32; i += 8)
        t[i][threadIdx.x] = W[(size_t)(y0 + i) * Hh + x0 + threadIdx.x];
    __syncthreads();
    #pragma unroll
    for (int i = threadIdx.y; i < 32; i += 8)
        Wt[(size_t)(x0 + i) * Dd + y0 + threadIdx.x] = __float2half(t[threadIdx.x][i]);
}

// ---------------- kernel 2: QKV projection, fp16 inputs / f32 acc ----------------
// CTA tile 128(r) x 128(h), K=256 in 4 chunks of k64. Warp tile 64x32. ldmatrix loads.
// grid: (Hh/128, (B*N)/128, 3)  block: 256
__global__ __launch_bounds__(256, 2) void qkv_mma_kernel(
    const float* __restrict__ bq, const float* __restrict__ bk, const float* __restrict__ bv)
{
    extern __shared__ float dynsm[];
    const uint32_t sb = smem_u32(dynsm);
    const int tid  = threadIdx.x;
    const int wid  = tid >> 5;
    const int lane = tid & 31;
    const int g = lane >> 2, t = lane & 3;
    const int wm = (wid & 1) * 64;
    const int wn = (wid >> 1) * 32;
    const int lr = tid >> 3;
    const int lc = tid & 7;

    const int z  = blockIdx.z;
    const float* bias = (z == 0) ? bq : (z == 1) ? bk : bv;
    const int r0 = blockIdx.y * 128;
    const int h0 = blockIdx.x * 128;

    const uint32_t stsOff = SW128((uint32_t)(lr * 128 + lc * 16));
    const __half* Aq = g_xh + (size_t)r0 * Dd + (size_t)lr * 256 + lc * 8;
    const __half* Bk = g_Wth + z * (Dd * Hh) + (size_t)h0 * Dd + (size_t)lr * 256 + lc * 8;

    // ldmatrix per-lane addressing
    const int quad = lane >> 3, rr = lane & 7;
    const uint32_t swzL = (uint32_t)rr << 4;
    const uint32_t aRowOff = (uint32_t)(wm + (quad & 1) * 8 + rr) * 128u;
    const uint32_t colSelA = (uint32_t)(quad >> 1) * 16u;
    const uint32_t bRowOff = (uint32_t)(wn + (quad >> 1) * 8 + rr) * 128u;
    const uint32_t colSelB = (uint32_t)(quad & 1) * 16u;

    float c[4][4][4];
    #pragma unroll
    for (int mt = 0; mt < 4; mt++)
        #pragma unroll
        for (int nt = 0; nt < 4; nt++)
            #pragma unroll
            for (int r = 0; r < 4; r++) c[mt][nt][r] = 0.0f;

    auto issue = [&](int ch, int buf) {
        const uint32_t ba = sb + (uint32_t)buf * 32768u;
        const __half* qa = Aq + ch * 64;
        const __half* ka = Bk + ch * 64;
        #pragma unroll
        for (int i = 0; i < 4; i++) {
            cpasync16(ba + stsOff + i * 4096u,          qa + (size_t)i * 32 * 256);
            cpasync16(ba + 16384u + stsOff + i * 4096u, ka + (size_t)i * 32 * 256);
        }
        CP_COMMIT();
    };
    auto compute = [&](int buf) {
        const uint32_t aB = sb + (uint32_t)buf * 32768u + aRowOff;
        const uint32_t bB = sb + (uint32_t)buf * 32768u + 16384u + bRowOff;
        #pragma unroll
        for (int ks = 0; ks < 4; ks++) {
            const uint32_t ctA = ((uint32_t)(ks * 32) + colSelA) ^ swzL;
            const uint32_t ctB = ((uint32_t)(ks * 32) + colSelB) ^ swzL;
            uint32_t b[4][2];
            #pragma unroll
            for (int np = 0; np < 2; np++)
                ldm_x4(b[2*np][0], b[2*np][1], b[2*np+1][0], b[2*np+1][1],
                       bB + np * 2048u + ctB);
            #pragma unroll
            for (int mt = 0; mt < 4; mt++) {
                uint32_t a0, a1, a2, a3;
                ldm_x4(a0, a1, a2, a3, aB + mt * 2048u + ctA);
                #pragma unroll
                for (int nt = 0; nt < 4; nt++)
                    mma_f16f32(c[mt][nt], a0, a1, a2, a3, b[nt][0], b[nt][1]);
            }
        }
    };

    issue(0, 0); issue(1, 1);
    #pragma unroll 1
    for (int ch = 0; ch < 4; ch++) {
        if (ch == 3) { CP_WAIT(0); } else { CP_WAIT(1); }
        __syncthreads();
        compute(ch & 1);
        __syncthreads();
        if (ch + 2 < 4) issue(ch + 2, ch & 1);
    }

    if (z == 2) {
        #pragma unroll
        for (int mt = 0; mt < 4; mt++) {
            const int row = r0 + wm + mt * 16 + g;
            #pragma unroll
            for (int nt = 0; nt < 4; nt++) {
                const int col = h0 + wn + nt * 8 + 2 * t;
                float2 bc = *reinterpret_cast<const float2*>(&bias[col]);
                float2 v0, v1;
                v0.x = c[mt][nt][0] + bc.x; v0.y = c[mt][nt][1] + bc.y;
                v1.x = c[mt][nt][2] + bc.x; v1.y = c[mt][nt][3] + bc.y;
                *reinterpret_cast<float2*>(&g_V[(size_t)row       * Hh + col]) = v0;
                *reinterpret_cast<float2*>(&g_V[(size_t)(row + 8) * Hh + col]) = v1;
            }
        }
    } else {
        __half* outh = (z == 0) ? g_Qh : g_Kh;
        #pragma unroll
        for (int mt = 0; mt < 4; mt++) {
            const int row = r0 + wm + mt * 16 + g;
            #pragma unroll
            for (int nt = 0; nt < 4; nt++) {
                const int col = h0 + wn + nt * 8 + 2 * t;
                float2 bc = *reinterpret_cast<const float2*>(&bias[col]);
                *reinterpret_cast<__half2*>(&outh[(size_t)row       * Hh + col]) =
                    __floats2half2_rn(c[mt][nt][0] + bc.x, c[mt][nt][1] + bc.y);
                *reinterpret_cast<__half2*>(&outh[(size_t)(row + 8) * Hh + col]) =
                    __floats2half2_rn(c[mt][nt][2] + bc.x, c[mt][nt][3] + bc.y);
            }
        }
    }
}

// ---------------- kernel 3: P = exp(Q K^T * scale), Z row-sums ----------------
// fp16 in, fp16 acc. CTA tile 128(q) x 256(k); warp tile 64x64; ldmatrix loads.
// Epilogue fully in packed half2: h2exp + hadd2 trees (1 MUFU / 2 values).
// grid: (N/256, N/128, B)  block: 256
__global__ __launch_bounds__(256, 2) void scores_fused_kernel() {
    extern __shared__ float dynsm[];
    __shared__ float rsum[128];
    const uint32_t sb = smem_u32(dynsm);
    const int tid  = threadIdx.x;
    const int wid  = tid >> 5;
    const int lane = tid & 31;
    const int g = lane >> 2, t = lane & 3;
    const int wm = (wid & 1) * 64;
    const int wn = (wid >> 1) * 64;
    const int lr = tid >> 3;
    const int lc = tid & 7;

    const int b  = blockIdx.z;
    const int q0 = blockIdx.y * 128;
    const int k0 = blockIdx.x * 256;

    const uint32_t stsOff = SW128((uint32_t)(lr * 128 + lc * 16));
    const __half* Aq = g_Qh + (size_t)(b * Nn + q0) * Hh + (size_t)lr * 256 + lc * 8;
    const __half* Bk = g_Kh + (size_t)(b * Nn + k0) * Hh + (size_t)lr * 256 + lc * 8;

    const int quad = lane >> 3, rr = lane & 7;
    const uint32_t swzL = (uint32_t)rr << 4;
    const uint32_t aRowOff = (uint32_t)(wm + (quad & 1) * 8 + rr) * 128u;
    const uint32_t colSelA = (uint32_t)(quad >> 1) * 16u;
    const uint32_t bRowOff = (uint32_t)(wn + (quad >> 1) * 8 + rr) * 128u;
    const uint32_t colSelB = (uint32_t)(quad & 1) * 16u;

    uint32_t c[4][8][2];   // f16x2 accumulators: 64 regs
    #pragma unroll
    for (int mt = 0; mt < 4; mt++)
        #pragma unroll
        for (int nt = 0; nt < 8; nt++) { c[mt][nt][0] = 0u; c[mt][nt][1] = 0u; }

    auto issue = [&](int ch, int buf) {
        const uint32_t ba = sb + (uint32_t)buf * 49152u;
        const __half* qa = Aq + ch * 64;
        const __half* ka = Bk + ch * 64;
        #pragma unroll
        for (int i = 0; i < 4; i++)
            cpasync16(ba + stsOff + i * 4096u, qa + (size_t)i * 32 * 256);
        #pragma unroll
        for (int i = 0; i < 8; i++)
            cpasync16(ba + 16384u + stsOff + i * 4096u, ka + (size_t)i * 32 * 256);
        CP_COMMIT();
    };
    auto compute = [&](int buf) {
        const uint32_t aB = sb + (uint32_t)buf * 49152u + aRowOff;
        const uint32_t bB = sb + (uint32_t)buf * 49152u + 16384u + bRowOff;
        #pragma unroll
        for (int ks = 0; ks < 4; ks++) {
            const uint32_t ctA = ((uint32_t)(ks * 32) + colSelA) ^ swzL;
            const uint32_t ctB = ((uint32_t)(ks * 32) + colSelB) ^ swzL;
            uint32_t b[8][2];
            #pragma unroll
            for (int np = 0; np < 4; np++)
                ldm_x4(b[2*np][0], b[2*np][1], b[2*np+1][0], b[2*np+1][1],
                       bB + np * 2048u + ctB);
            #pragma unroll
            for (int mt = 0; mt < 4; mt++) {
                uint32_t a0, a1, a2, a3;
                ldm_x4(a0, a1, a2, a3, aB + mt * 2048u + ctA);
                #pragma unroll
                for (int nt = 0; nt < 8; nt++)
                    mma_f16(c[mt][nt], a0, a1, a2, a3, b[nt][0], b[nt][1]);
            }
        }
    };

    issue(0, 0); issue(1, 1);
    #pragma unroll 1
    for (int ch = 0; ch < 4; ch++) {
        if (ch == 3) { CP_WAIT(0); } else { CP_WAIT(1); }
        __syncthreads();
        compute(ch & 1);
        __syncthreads();
        if (ch + 2 < 4) issue(ch + 2, ch & 1);
    }

    // ---- fused epilogue: packed-half2 exp, direct fp16 store, Z partials ----
    if (tid < 128) rsum[tid] = 0.0f;
    __syncthreads();

    const __half2 scale2 = __float2half2_rn(0.0625f);   // 1/sqrt(256)
    __half* Ph = g_P + (size_t)(b * Nn) * Nn;

    #pragma unroll
    for (int mt = 0; mt < 4; mt++) {
        const int row = wm + mt * 16 + g;
        __half2 e0[8], e1[8];
        #pragma unroll
        for (int nt = 0; nt < 8; nt++) {
            const int col = k0 + wn + nt * 8 + 2 * t;
            __half2 c0 = *reinterpret_cast<__half2*>(&c[mt][nt][0]);
            __half2 c1 = *reinterpret_cast<__half2*>(&c[mt][nt][1]);
            e0[nt] = h2exp(__hmul2(c0, scale2));
            e1[nt] = h2exp(__hmul2(c1, scale2));
            *reinterpret_cast<__half2*>(&Ph[(size_t)(q0 + row)     * Nn + col]) = e0[nt];
            *reinterpret_cast<__half2*>(&Ph[(size_t)(q0 + row + 8) * Nn + col]) = e1[nt];
        }
        // hadd2 trees (16 values each; max sum ~900 << f16 max)
        __half2 t0 = __hadd2(__hadd2(__hadd2(e0[0], e0[1]), __hadd2(e0[2], e0[3])),
                             __hadd2(__hadd2(e0[4], e0[5]), __hadd2(e0[6], e0[7])));
        __half2 t1 = __hadd2(__hadd2(__hadd2(e1[0], e1[1]), __hadd2(e1[2], e1[3])),
                             __hadd2(__hadd2(e1[4], e1[5]), __hadd2(e1[6], e1[7])));
        float2 f0 = __half22float2(t0);
        float2 f1 = __half22float2(t1);
        float s0 = f0.x + f0.y;
        float s1 = f1.x + f1.y;
        s0 += __shfl_xor_sync(0xFFFFFFFFu, s0, 1);
        s0 += __shfl_xor_sync(0xFFFFFFFFu, s0, 2);
        s1 += __shfl_xor_sync(0xFFFFFFFFu, s1, 1);
        s1 += __shfl_xor_sync(0xFFFFFFFFu, s1, 2);
        if (t == 0) {
            atomicAdd(&rsum[row],     s0);
            atomicAdd(&rsum[row + 8], s1);
        }
    }
    __syncthreads();
    if (tid < 128) atomicAdd(&g_z[b * Nn + q0 + tid], rsum[tid]);
}

// ---------------- kernel 4: w[b,k] = sum_q P[q,k] / Z[q]  (invZ fused) ----------------
__global__ __launch_bounds__(128) void colsum_kernel() {
    const int b  = blockIdx.z;
    const int k2 = blockIdx.x * 128 + threadIdx.x;
    const int q0 = blockIdx.y * 256;

    __shared__ float iz[256];
    if (threadIdx.x < 128) {
        iz[threadIdx.x]       = 1.0f / g_z[b * Nn + q0 + threadIdx.x];
        iz[threadIdx.x + 128] = 1.0f / g_z[b * Nn + q0 + 128 + threadIdx.x];
    }
    __syncthreads();

    const __half2* Pb = reinterpret_cast<const __half2*>(g_P + (size_t)(b * Nn) * Nn);

    float ax = 0.0f, ay = 0.0f;
    #pragma unroll 4
    for (int q = 0; q < 256; q++) {
        float2 v = __half22float2(Pb[(size_t)(q0 + q) * (Nn / 2) + k2]);
        float w = iz[q];
        ax += v.x * w;
        ay += v.y * w;
    }
    atomicAdd(&g_w[b * Nn + 2 * k2],     ax);
    atomicAdd(&g_w[b * Nn + 2 * k2 + 1], ay);
}

// ---------------- kernel 5: out[b,h] = (1/N) sum_k w[b,k] V[b,k,h] ----------------
__global__ __launch_bounds__(256) void out_kernel(float* __restrict__ out) {
    const int b  = blockIdx.x;
    const int ks = blockIdx.y;
    const int h  = threadIdx.x;
    const float* Vb = g_V + (size_t)b * Nn * Hh;

    float acc = 0.0f;
    #pragma unroll 8
    for (int k = ks * 256; k < ks * 256 + 256; k++)
        acc += g_w[b * Nn + k] * Vb[(size_t)k * Hh + h];

    atomicAdd(&out[b * Hh + h], acc * (1.0f / Nn));
}

// ---------------- launch ----------------
extern "C" void kernel_launch(void* const* d_in, const int* in_sizes, int n_in,
                              void* d_out, int out_size) {
    const float* x  = (const float*)d_in[0];
    const float* Wq = (const float*)d_in[1];
    const float* bq = (const float*)d_in[2];
    const float* Wk = (const float*)d_in[3];
    const float* bk = (const float*)d_in[4];
    const float* Wv = (const float*)d_in[5];
    const float* bv = (const float*)d_in[6];
    float* out = (float*)d_out;

    cudaFuncSetAttribute(qkv_mma_kernel,
                         cudaFuncAttributeMaxDynamicSharedMemorySize, QKV_DYN_SMEM);
    cudaFuncSetAttribute(scores_fused_kernel,
                         cudaFuncAttributeMaxDynamicSharedMemorySize, SC_DYN_SMEM);

    convert_x_kernel<<<(Bb * Nn * Dd / 2) / 256, 256>>>(x, out);
    transpose_w_kernel<<<dim3(8, 8, 3), dim3(32, 8)>>>(Wq, Wk, Wv);
    qkv_mma_kernel<<<dim3(Hh / 128, (Bb * Nn) / 128, 3), 256, QKV_DYN_SMEM>>>(bq, bk, bv);
    scores_fused_kernel<<<dim3(Nn / 256, Nn / 128, Bb), 256, SC_DYN_SMEM>>>();
    colsum_kernel<<<dim3(Nn / 256, Nn / 256, Bb), 128>>>();
    out_kernel<<<dim3(Bb, 16), 256>>>(out);
}

// round 16
// speedup vs baseline: 1.1146x; 1.0787x over previous
#include <cuda_runtime.h>
#include <cuda_fp16.h>
#include <math.h>
#include <stdint.h>

#define Bb 8
#define Nn 4096
#define Dd 256
#define Hh 256

// ---------------- static device scratch (allocation-free) ----------------
__device__ __half g_xh[(size_t)Bb * Nn * Dd];            // 16.8 MB  x in fp16
__device__ __half g_Qh[(size_t)Bb * Nn * Hh];            // 16.8 MB  Q in fp16
__device__ __half g_Kh[(size_t)Bb * Nn * Hh];            // 16.8 MB  K in fp16
__device__ float  g_V[(size_t)Bb * Nn * Hh];             // 33.5 MB  V fp32
__device__ __half g_P[(size_t)Bb * Nn * Nn];             // 268 MB: P = exp(S) fp16
__device__ __half g_Wth[3 * Dd * Hh];                    // W^T fp16 for Q,K,V
__device__ float  g_z[Bb * Nn];                          // row sums Z
__device__ float  g_w[Bb * Nn];                          // column weights

// ================= helpers =================
__device__ __forceinline__ uint32_t smem_u32(const void* p) {
    uint32_t a;
    asm("{ .reg .u64 t; cvta.to.shared.u64 t, %1; cvt.u32.u64 %0, t; }" : "=r"(a) : "l"(p));
    return a;
}
__device__ __forceinline__ void cpasync16(uint32_t dst, const void* src) {
    asm volatile("cp.async.ca.shared.global [%0], [%1], 16;" :: "r"(dst), "l"(src));
}
#define CP_COMMIT() asm volatile("cp.async.commit_group;" ::: "memory")
#define CP_WAIT(N)  asm volatile("cp.async.wait_group %0;" :: "n"(N) : "memory")

__device__ __forceinline__ void ldm_x4(uint32_t& r0, uint32_t& r1, uint32_t& r2, uint32_t& r3,
                                       uint32_t addr) {
    asm volatile("ldmatrix.sync.aligned.m8n8.x4.shared.b16 {%0,%1,%2,%3}, [%4];"
                 : "=r"(r0), "=r"(r1), "=r"(r2), "=r"(r3) : "r"(addr));
}
// fp16 inputs, fp32 accumulate (QKV projection)
__device__ __forceinline__ void mma_f16f32(float* c,
                                           uint32_t a0, uint32_t a1, uint32_t a2, uint32_t a3,
                                           uint32_t b0, uint32_t b1) {
    asm volatile(
        "mma.sync.aligned.m16n8k16.row.col.f32.f16.f16.f32 "
        "{%0,%1,%2,%3}, {%4,%5,%6,%7}, {%8,%9}, {%0,%1,%2,%3};"
        : "+f"(c[0]), "+f"(c[1]), "+f"(c[2]), "+f"(c[3])
        : "r"(a0), "r"(a1), "r"(a2), "r"(a3), "r"(b0), "r"(b1));
}
// fp16 inputs, fp16 accumulate (scores)
__device__ __forceinline__ void mma_f16(uint32_t* c,
                                        uint32_t a0, uint32_t a1, uint32_t a2, uint32_t a3,
                                        uint32_t b0, uint32_t b1) {
    asm volatile(
        "mma.sync.aligned.m16n8k16.row.col.f16.f16.f16.f16 "
        "{%0,%1}, {%2,%3,%4,%5}, {%6,%7}, {%0,%1};"
        : "+r"(c[0]), "+r"(c[1])
        : "r"(a0), "r"(a1), "r"(a2), "r"(a3), "r"(b0), "r"(b1));
}
#define SW128(o) ((o) ^ (((o) >> 3) & 0x70u))

#define QKV_DYN_SMEM 65536    // 2 buffers x (A 16KB + B 16KB)
#define SC_DYN_SMEM  98304    // 2 buffers x (A 16KB + B 32KB); epilogue reuses as P stage
#define PS_STRIDE    132      // half2 words per staged P row (bank-conflict-free: 4g+t)

// ---------------- kernel 0: x -> fp16 (+ zero accumulators) ----------------
__global__ __launch_bounds__(256) void convert_x_kernel(const float* __restrict__ x,
                                                        float* __restrict__ out) {
    int i = blockIdx.x * 256 + threadIdx.x;           // one float2 -> half2
    float2 v = reinterpret_cast<const float2*>(x)[i];
    reinterpret_cast<__half2*>(g_xh)[i] = __floats2half2_rn(v.x, v.y);
    if (i < Bb * Nn) { g_w[i] = 0.0f; g_z[i] = 0.0f; }
    if (i < Bb * Hh) out[i] = 0.0f;
}

// ---------------- kernel 1: W transpose -> fp16 ----------------
__global__ void transpose_w_kernel(const float* __restrict__ Wq,
                                   const float* __restrict__ Wk,
                                   const float* __restrict__ Wv) {
    const float* W = (blockIdx.z == 0) ? Wq : (blockIdx.z == 1) ? Wk : Wv;
    __half* Wt = g_Wth + blockIdx.z * (Dd * Hh);
    __shared__ float t[32][33];
    const int x0 = blockIdx.x * 32, y0 = blockIdx.y * 32;
    #pragma unroll
    for (int i = threadIdx.y; i < 32; i += 8)
        t[i][threadIdx.x] = W[(size_t)(y0 + i) * Hh + x0 + threadIdx.x];
    __syncthreads();
    #pragma unroll
    for (int i = threadIdx.y; i < 32; i += 8)
        Wt[(size_t)(x0 + i) * Dd + y0 + threadIdx.x] = __float2half(t[threadIdx.x][i]);
}

// ---------------- kernel 2: QKV projection, fp16 inputs / f32 acc ----------------
// CTA tile 128(r) x 128(h), K=256 in 4 chunks of k64. Warp tile 64x32. ldmatrix loads.
// grid: (Hh/128, (B*N)/128, 3)  block: 256
__global__ __launch_bounds__(256, 2) void qkv_mma_kernel(
    const float* __restrict__ bq, const float* __restrict__ bk, const float* __restrict__ bv)
{
    extern __shared__ float dynsm[];
    const uint32_t sb = smem_u32(dynsm);
    const int tid  = threadIdx.x;
    const int wid  = tid >> 5;
    const int lane = tid & 31;
    const int g = lane >> 2, t = lane & 3;
    const int wm = (wid & 1) * 64;
    const int wn = (wid >> 1) * 32;
    const int lr = tid >> 3;
    const int lc = tid & 7;

    const int z  = blockIdx.z;
    const float* bias = (z == 0) ? bq : (z == 1) ? bk : bv;
    const int r0 = blockIdx.y * 128;
    const int h0 = blockIdx.x * 128;

    const uint32_t stsOff = SW128((uint32_t)(lr * 128 + lc * 16));
    const __half* Aq = g_xh + (size_t)r0 * Dd + (size_t)lr * 256 + lc * 8;
    const __half* Bk = g_Wth + z * (Dd * Hh) + (size_t)h0 * Dd + (size_t)lr * 256 + lc * 8;

    // ldmatrix per-lane addressing
    const int quad = lane >> 3, rr = lane & 7;
    const uint32_t swzL = (uint32_t)rr << 4;
    const uint32_t aRowOff = (uint32_t)(wm + (quad & 1) * 8 + rr) * 128u;
    const uint32_t colSelA = (uint32_t)(quad >> 1) * 16u;
    const uint32_t bRowOff = (uint32_t)(wn + (quad >> 1) * 8 + rr) * 128u;
    const uint32_t colSelB = (uint32_t)(quad & 1) * 16u;

    float c[4][4][4];
    #pragma unroll
    for (int mt = 0; mt < 4; mt++)
        #pragma unroll
        for (int nt = 0; nt < 4; nt++)
            #pragma unroll
            for (int r = 0; r < 4; r++) c[mt][nt][r] = 0.0f;

    auto issue = [&](int ch, int buf) {
        const uint32_t ba = sb + (uint32_t)buf * 32768u;
        const __half* qa = Aq + ch * 64;
        const __half* ka = Bk + ch * 64;
        #pragma unroll
        for (int i = 0; i < 4; i++) {
            cpasync16(ba + stsOff + i * 4096u,          qa + (size_t)i * 32 * 256);
            cpasync16(ba + 16384u + stsOff + i * 4096u, ka + (size_t)i * 32 * 256);
        }
        CP_COMMIT();
    };
    auto compute = [&](int buf) {
        const uint32_t aB = sb + (uint32_t)buf * 32768u + aRowOff;
        const uint32_t bB = sb + (uint32_t)buf * 32768u + 16384u + bRowOff;
        #pragma unroll
        for (int ks = 0; ks < 4; ks++) {
            const uint32_t ctA = ((uint32_t)(ks * 32) + colSelA) ^ swzL;
            const uint32_t ctB = ((uint32_t)(ks * 32) + colSelB) ^ swzL;
            uint32_t b[4][2];
            #pragma unroll
            for (int np = 0; np < 2; np++)
                ldm_x4(b[2*np][0], b[2*np][1], b[2*np+1][0], b[2*np+1][1],
                       bB + np * 2048u + ctB);
            #pragma unroll
            for (int mt = 0; mt < 4; mt++) {
                uint32_t a0, a1, a2, a3;
                ldm_x4(a0, a1, a2, a3, aB + mt * 2048u + ctA);
                #pragma unroll
                for (int nt = 0; nt < 4; nt++)
                    mma_f16f32(c[mt][nt], a0, a1, a2, a3, b[nt][0], b[nt][1]);
            }
        }
    };

    issue(0, 0); issue(1, 1);
    #pragma unroll 1
    for (int ch = 0; ch < 4; ch++) {
        if (ch == 3) { CP_WAIT(0); } else { CP_WAIT(1); }
        __syncthreads();
        compute(ch & 1);
        __syncthreads();
        if (ch + 2 < 4) issue(ch + 2, ch & 1);
    }

    if (z == 2) {
        #pragma unroll
        for (int mt = 0; mt < 4; mt++) {
            const int row = r0 + wm + mt * 16 + g;
            #pragma unroll
            for (int nt = 0; nt < 4; nt++) {
                const int col = h0 + wn + nt * 8 + 2 * t;
                float2 bc = *reinterpret_cast<const float2*>(&bias[col]);
                float2 v0, v1;
                v0.x = c[mt][nt][0] + bc.x; v0.y = c[mt][nt][1] + bc.y;
                v1.x = c[mt][nt][2] + bc.x; v1.y = c[mt][nt][3] + bc.y;
                *reinterpret_cast<float2*>(&g_V[(size_t)row       * Hh + col]) = v0;
                *reinterpret_cast<float2*>(&g_V[(size_t)(row + 8) * Hh + col]) = v1;
            }
        }
    } else {
        __half* outh = (z == 0) ? g_Qh : g_Kh;
        #pragma unroll
        for (int mt = 0; mt < 4; mt++) {
            const int row = r0 + wm + mt * 16 + g;
            #pragma unroll
            for (int nt = 0; nt < 4; nt++) {
                const int col = h0 + wn + nt * 8 + 2 * t;
                float2 bc = *reinterpret_cast<const float2*>(&bias[col]);
                *reinterpret_cast<__half2*>(&outh[(size_t)row       * Hh + col]) =
                    __floats2half2_rn(c[mt][nt][0] + bc.x, c[mt][nt][1] + bc.y);
                *reinterpret_cast<__half2*>(&outh[(size_t)(row + 8) * Hh + col]) =
                    __floats2half2_rn(c[mt][nt][2] + bc.x, c[mt][nt][3] + bc.y);
            }
        }
    }
}

// ---------------- kernel 3: P = exp(Q K^T * scale), Z row-sums ----------------
// fp16 in, fp16 acc. CTA tile 128(q) x 256(k); warp tile 64x64; ldmatrix loads.
// Epilogue: packed-half2 exp -> smem stage (conflict-free) -> coalesced STG.128.
// grid: (N/256, N/128, B)  block: 256
__global__ __launch_bounds__(256, 2) void scores_fused_kernel() {
    extern __shared__ float dynsm[];
    __shared__ float rsum[128];
    const uint32_t sb = smem_u32(dynsm);
    const int tid  = threadIdx.x;
    const int wid  = tid >> 5;
    const int lane = tid & 31;
    const int g = lane >> 2, t = lane & 3;
    const int wm = (wid & 1) * 64;
    const int wn = (wid >> 1) * 64;
    const int lr = tid >> 3;
    const int lc = tid & 7;

    const int b  = blockIdx.z;
    const int q0 = blockIdx.y * 128;
    const int k0 = blockIdx.x * 256;

    const uint32_t stsOff = SW128((uint32_t)(lr * 128 + lc * 16));
    const __half* Aq = g_Qh + (size_t)(b * Nn + q0) * Hh + (size_t)lr * 256 + lc * 8;
    const __half* Bk = g_Kh + (size_t)(b * Nn + k0) * Hh + (size_t)lr * 256 + lc * 8;

    const int quad = lane >> 3, rr = lane & 7;
    const uint32_t swzL = (uint32_t)rr << 4;
    const uint32_t aRowOff = (uint32_t)(wm + (quad & 1) * 8 + rr) * 128u;
    const uint32_t colSelA = (uint32_t)(quad >> 1) * 16u;
    const uint32_t bRowOff = (uint32_t)(wn + (quad >> 1) * 8 + rr) * 128u;
    const uint32_t colSelB = (uint32_t)(quad & 1) * 16u;

    uint32_t c[4][8][2];   // f16x2 accumulators: 64 regs
    #pragma unroll
    for (int mt = 0; mt < 4; mt++)
        #pragma unroll
        for (int nt = 0; nt < 8; nt++) { c[mt][nt][0] = 0u; c[mt][nt][1] = 0u; }

    auto issue = [&](int ch, int buf) {
        const uint32_t ba = sb + (uint32_t)buf * 49152u;
        const __half* qa = Aq + ch * 64;
        const __half* ka = Bk + ch * 64;
        #pragma unroll
        for (int i = 0; i < 4; i++)
            cpasync16(ba + stsOff + i * 4096u, qa + (size_t)i * 32 * 256);
        #pragma unroll
        for (int i = 0; i < 8; i++)
            cpasync16(ba + 16384u + stsOff + i * 4096u, ka + (size_t)i * 32 * 256);
        CP_COMMIT();
    };
    auto compute = [&](int buf) {
        const uint32_t aB = sb + (uint32_t)buf * 49152u + aRowOff;
        const uint32_t bB = sb + (uint32_t)buf * 49152u + 16384u + bRowOff;
        #pragma unroll
        for (int ks = 0; ks < 4; ks++) {
            const uint32_t ctA = ((uint32_t)(ks * 32) + colSelA) ^ swzL;
            const uint32_t ctB = ((uint32_t)(ks * 32) + colSelB) ^ swzL;
            uint32_t b[8][2];
            #pragma unroll
            for (int np = 0; np < 4; np++)
                ldm_x4(b[2*np][0], b[2*np][1], b[2*np+1][0], b[2*np+1][1],
                       bB + np * 2048u + ctB);
            #pragma unroll
            for (int mt = 0; mt < 4; mt++) {
                uint32_t a0, a1, a2, a3;
                ldm_x4(a0, a1, a2, a3, aB + mt * 2048u + ctA);
                #pragma unroll
                for (int nt = 0; nt < 8; nt++)
                    mma_f16(c[mt][nt], a0, a1, a2, a3, b[nt][0], b[nt][1]);
            }
        }
    };

    issue(0, 0); issue(1, 1);
    #pragma unroll 1
    for (int ch = 0; ch < 4; ch++) {
        if (ch == 3) { CP_WAIT(0); } else { CP_WAIT(1); }
        __syncthreads();
        compute(ch & 1);
        __syncthreads();
        if (ch + 2 < 4) issue(ch + 2, ch & 1);
    }

    // ---- epilogue part 1: half2 exp -> smem stage (conflict-free), Z partials ----
    if (tid < 128) rsum[tid] = 0.0f;
    __syncthreads();

    __half2* Ps = reinterpret_cast<__half2*>(dynsm);   // [128][PS_STRIDE] half2 tile
    const __half2 scale2 = __float2half2_rn(0.0625f);  // 1/sqrt(256)
    const int wn2 = wn >> 1;

    #pragma unroll
    for (int mt = 0; mt < 4; mt++) {
        const int row = wm + mt * 16 + g;
        __half2 e0[8], e1[8];
        #pragma unroll
        for (int nt = 0; nt < 8; nt++) {
            __half2 c0 = *reinterpret_cast<__half2*>(&c[mt][nt][0]);
            __half2 c1 = *reinterpret_cast<__half2*>(&c[mt][nt][1]);
            e0[nt] = h2exp(__hmul2(c0, scale2));
            e1[nt] = h2exp(__hmul2(c1, scale2));
            Ps[(row)     * PS_STRIDE + wn2 + nt * 4 + t] = e0[nt];
            Ps[(row + 8) * PS_STRIDE + wn2 + nt * 4 + t] = e1[nt];
        }
        // hadd2 trees (16 values each; max sum ~900 << f16 max)
        __half2 t0 = __hadd2(__hadd2(__hadd2(e0[0], e0[1]), __hadd2(e0[2], e0[3])),
                             __hadd2(__hadd2(e0[4], e0[5]), __hadd2(e0[6], e0[7])));
        __half2 t1 = __hadd2(__hadd2(__hadd2(e1[0], e1[1]), __hadd2(e1[2], e1[3])),
                             __hadd2(__hadd2(e1[4], e1[5]), __hadd2(e1[6], e1[7])));
        float2 f0 = __half22float2(t0);
        float2 f1 = __half22float2(t1);
        float s0 = f0.x + f0.y;
        float s1 = f1.x + f1.y;
        s0 += __shfl_xor_sync(0xFFFFFFFFu, s0, 1);
        s0 += __shfl_xor_sync(0xFFFFFFFFu, s0, 2);
        s1 += __shfl_xor_sync(0xFFFFFFFFu, s1, 1);
        s1 += __shfl_xor_sync(0xFFFFFFFFu, s1, 2);
        if (t == 0) {
            atomicAdd(&rsum[row],     s0);
            atomicAdd(&rsum[row + 8], s1);
        }
    }
    __syncthreads();

    // ---- epilogue part 2: coalesced write-out (STG.128), Z flush ----
    __half* Ph = g_P + (size_t)(b * Nn) * Nn;
    #pragma unroll 4
    for (int i = tid; i < 128 * 32; i += 256) {
        const int row = i >> 5;          // 0..127
        const int u4  = i & 31;          // uint4 index within row (32 x 16B = 512B)
        uint4 v = *reinterpret_cast<const uint4*>(&Ps[row * PS_STRIDE + u4 * 4]);
        *reinterpret_cast<uint4*>(&Ph[(size_t)(q0 + row) * Nn + k0 + u4 * 8]) = v;
    }
    if (tid < 128) atomicAdd(&g_z[b * Nn + q0 + tid], rsum[tid]);
}

// ---------------- kernel 4: w[b,k] = sum_q P[q,k] / Z[q]  (invZ fused) ----------------
__global__ __launch_bounds__(128) void colsum_kernel() {
    const int b  = blockIdx.z;
    const int k2 = blockIdx.x * 128 + threadIdx.x;
    const int q0 = blockIdx.y * 256;

    __shared__ float iz[256];
    if (threadIdx.x < 128) {
        iz[threadIdx.x]       = 1.0f / g_z[b * Nn + q0 + threadIdx.x];
        iz[threadIdx.x + 128] = 1.0f / g_z[b * Nn + q0 + 128 + threadIdx.x];
    }
    __syncthreads();

    const __half2* Pb = reinterpret_cast<const __half2*>(g_P + (size_t)(b * Nn) * Nn);

    float ax = 0.0f, ay = 0.0f;
    #pragma unroll 4
    for (int q = 0; q < 256; q++) {
        float2 v = __half22float2(Pb[(size_t)(q0 + q) * (Nn / 2) + k2]);
        float w = iz[q];
        ax += v.x * w;
        ay += v.y * w;
    }
    atomicAdd(&g_w[b * Nn + 2 * k2],     ax);
    atomicAdd(&g_w[b * Nn + 2 * k2 + 1], ay);
}

// ---------------- kernel 5: out[b,h] = (1/N) sum_k w[b,k] V[b,k,h] ----------------
__global__ __launch_bounds__(256) void out_kernel(float* __restrict__ out) {
    const int b  = blockIdx.x;
    const int ks = blockIdx.y;
    const int h  = threadIdx.x;
    const float* Vb = g_V + (size_t)b * Nn * Hh;

    float acc = 0.0f;
    #pragma unroll 8
    for (int k = ks * 256; k < ks * 256 + 256; k++)
        acc += g_w[b * Nn + k] * Vb[(size_t)k * Hh + h];

    atomicAdd(&out[b * Hh + h], acc * (1.0f / Nn));
}

// ---------------- launch ----------------
extern "C" void kernel_launch(void* const* d_in, const int* in_sizes, int n_in,
                              void* d_out, int out_size) {
    const float* x  = (const float*)d_in[0];
    const float* Wq = (const float*)d_in[1];
    const float* bq = (const float*)d_in[2];
    const float* Wk = (const float*)d_in[3];
    const float* bk = (const float*)d_in[4];
    const float* Wv = (const float*)d_in[5];
    const float* bv = (const float*)d_in[6];
    float* out = (float*)d_out;

    cudaFuncSetAttribute(qkv_mma_kernel,
                         cudaFuncAttributeMaxDynamicSharedMemorySize, QKV_DYN_SMEM);
    cudaFuncSetAttribute(scores_fused_kernel,
                         cudaFuncAttributeMaxDynamicSharedMemorySize, SC_DYN_SMEM);

    convert_x_kernel<<<(Bb * Nn * Dd / 2) / 256, 256>>>(x, out);
    transpose_w_kernel<<<dim3(8, 8, 3), dim3(32, 8)>>>(Wq, Wk, Wv);
    qkv_mma_kernel<<<dim3(Hh / 128, (Bb * Nn) / 128, 3), 256, QKV_DYN_SMEM>>>(bq, bk, bv);
    scores_fused_kernel<<<dim3(Nn / 256, Nn / 128, Bb), 256, SC_DYN_SMEM>>>();
    colsum_kernel<<<dim3(Nn / 256, Nn / 256, Bb), 128>>>();
    out_kernel<<<dim3(Bb, 16), 256>>>(out);
}

// round 17
// speedup vs baseline: 1.1344x; 1.0177x over previous
#include <cuda_runtime.h>
#include <cuda_fp16.h>
#include <math.h>
#include <stdint.h>

#define Bb 8
#define Nn 4096
#define Dd 256
#define Hh 256

// ---------------- static device scratch (allocation-free) ----------------
__device__ __half  g_xh[(size_t)Bb * Nn * Dd];           // x fp16
__device__ __half  g_Qh[(size_t)Bb * Nn * Hh];           // Q fp16
__device__ __half  g_Kh[(size_t)Bb * Nn * Hh];           // K fp16
__device__ __half  g_Vh[(size_t)Bb * Nn * Hh];           // V fp16
__device__ uint8_t g_P8[(size_t)Bb * Nn * Nn];           // 134 MB: P^T = exp(S)^T e4m3, [b][k][q]
__device__ __half  g_Wth[3 * Dd * Hh];                   // W^T fp16
__device__ float   g_z[Bb * Nn];                         // row sums Z
__device__ float   g_w[Bb * Nn];                         // column weights (x4096)
__device__ uint8_t g_chi[Bb * Nn];                       // c' hi e4m3
__device__ uint8_t g_clo[Bb * Nn];                       // c' lo e4m3

// ================= helpers =================
__device__ __forceinline__ uint32_t smem_u32(const void* p) {
    uint32_t a;
    asm("{ .reg .u64 t; cvta.to.shared.u64 t, %1; cvt.u32.u64 %0, t; }" : "=r"(a) : "l"(p));
    return a;
}
__device__ __forceinline__ void cpasync16(uint32_t dst, const void* src) {
    asm volatile("cp.async.ca.shared.global [%0], [%1], 16;" :: "r"(dst), "l"(src));
}
#define CP_COMMIT() asm volatile("cp.async.commit_group;" ::: "memory")
#define CP_WAIT(N)  asm volatile("cp.async.wait_group %0;" :: "n"(N) : "memory")

__device__ __forceinline__ void ldm_x4(uint32_t& r0, uint32_t& r1, uint32_t& r2, uint32_t& r3,
                                       uint32_t addr) {
    asm volatile("ldmatrix.sync.aligned.m8n8.x4.shared.b16 {%0,%1,%2,%3}, [%4];"
                 : "=r"(r0), "=r"(r1), "=r"(r2), "=r"(r3) : "r"(addr));
}
__device__ __forceinline__ void mma_f16f32(float* c,
                                           uint32_t a0, uint32_t a1, uint32_t a2, uint32_t a3,
                                           uint32_t b0, uint32_t b1) {
    asm volatile(
        "mma.sync.aligned.m16n8k16.row.col.f32.f16.f16.f32 "
        "{%0,%1,%2,%3}, {%4,%5,%6,%7}, {%8,%9}, {%0,%1,%2,%3};"
        : "+f"(c[0]), "+f"(c[1]), "+f"(c[2]), "+f"(c[3])
        : "r"(a0), "r"(a1), "r"(a2), "r"(a3), "r"(b0), "r"(b1));
}
__device__ __forceinline__ void mma_f16(uint32_t* c,
                                        uint32_t a0, uint32_t a1, uint32_t a2, uint32_t a3,
                                        uint32_t b0, uint32_t b1) {
    asm volatile(
        "mma.sync.aligned.m16n8k16.row.col.f16.f16.f16.f16 "
        "{%0,%1}, {%2,%3,%4,%5}, {%6,%7}, {%0,%1};"
        : "+r"(c[0]), "+r"(c[1])
        : "r"(a0), "r"(a1), "r"(a2), "r"(a3), "r"(b0), "r"(b1));
}
__device__ __forceinline__ void mma_fp8(float* c,
                                        uint32_t a0, uint32_t a1, uint32_t a2, uint32_t a3,
                                        uint32_t b0, uint32_t b1) {
    asm volatile(
        "mma.sync.aligned.m16n8k32.row.col.f32.e4m3.e4m3.f32 "
        "{%0,%1,%2,%3}, {%4,%5,%6,%7}, {%8,%9}, {%0,%1,%2,%3};"
        : "+f"(c[0]), "+f"(c[1]), "+f"(c[2]), "+f"(c[3])
        : "r"(a0), "r"(a1), "r"(a2), "r"(a3), "r"(b0), "r"(b1));
}
__device__ __forceinline__ uint16_t h2_to_e4m3x2(uint32_t h2) {
    uint16_t r;
    asm("cvt.rn.satfinite.e4m3x2.f16x2 %0, %1;" : "=h"(r) : "r"(h2));
    return r;
}
__device__ __forceinline__ void sts16(uint32_t addr, uint16_t v) {
    asm volatile("st.shared.u16 [%0], %1;" :: "r"(addr), "h"(v) : "memory");
}
#define SW128(o) ((o) ^ (((o) >> 3) & 0x70u))

#define QKV_DYN_SMEM 65536
#define SC_DYN_SMEM  98304
#define PT_STRIDE    272       // bytes per staged P^T row (68 words; 4g+c bank spread)

// ---------------- kernel 0: x -> fp16 (+ zero accumulators) ----------------
__global__ __launch_bounds__(256) void convert_x_kernel(const float* __restrict__ x,
                                                        float* __restrict__ out) {
    int i = blockIdx.x * 256 + threadIdx.x;
    float2 v = reinterpret_cast<const float2*>(x)[i];
    reinterpret_cast<__half2*>(g_xh)[i] = __floats2half2_rn(v.x, v.y);
    if (i < Bb * Nn) g_z[i] = 0.0f;
    if (i < Bb * Hh) out[i] = 0.0f;
}

// ---------------- kernel 1: W transpose -> fp16 ----------------
__global__ void transpose_w_kernel(const float* __restrict__ Wq,
                                   const float* __restrict__ Wk,
                                   const float* __restrict__ Wv) {
    const float* W = (blockIdx.z == 0) ? Wq : (blockIdx.z == 1) ? Wk : Wv;
    __half* Wt = g_Wth + blockIdx.z * (Dd * Hh);
    __shared__ float t[32][33];
    const int x0 = blockIdx.x * 32, y0 = blockIdx.y * 32;
    #pragma unroll
    for (int i = threadIdx.y; i < 32; i += 8)
        t[i][threadIdx.x] = W[(size_t)(y0 + i) * Hh + x0 + threadIdx.x];
    __syncthreads();
    #pragma unroll
    for (int i = threadIdx.y; i < 32; i += 8)
        Wt[(size_t)(x0 + i) * Dd + y0 + threadIdx.x] = __float2half(t[threadIdx.x][i]);
}

// ---------------- kernel 2: QKV projection, fp16 in / f32 acc, fp16 out ----------------
// grid: (Hh/128, (B*N)/128, 3)  block: 256
__global__ __launch_bounds__(256, 2) void qkv_mma_kernel(
    const float* __restrict__ bq, const float* __restrict__ bk, const float* __restrict__ bv)
{
    extern __shared__ float dynsm[];
    const uint32_t sb = smem_u32(dynsm);
    const int tid  = threadIdx.x;
    const int wid  = tid >> 5;
    const int lane = tid & 31;
    const int g = lane >> 2, t = lane & 3;
    const int wm = (wid & 1) * 64;
    const int wn = (wid >> 1) * 32;
    const int lr = tid >> 3;
    const int lc = tid & 7;

    const int z  = blockIdx.z;
    const float* bias = (z == 0) ? bq : (z == 1) ? bk : bv;
    __half* outh = (z == 0) ? g_Qh : (z == 1) ? g_Kh : g_Vh;
    const int r0 = blockIdx.y * 128;
    const int h0 = blockIdx.x * 128;

    const uint32_t stsOff = SW128((uint32_t)(lr * 128 + lc * 16));
    const __half* Aq = g_xh + (size_t)r0 * Dd + (size_t)lr * 256 + lc * 8;
    const __half* Bk = g_Wth + z * (Dd * Hh) + (size_t)h0 * Dd + (size_t)lr * 256 + lc * 8;

    const int quad = lane >> 3, rr = lane & 7;
    const uint32_t swzL = (uint32_t)rr << 4;
    const uint32_t aRowOff = (uint32_t)(wm + (quad & 1) * 8 + rr) * 128u;
    const uint32_t colSelA = (uint32_t)(quad >> 1) * 16u;
    const uint32_t bRowOff = (uint32_t)(wn + (quad >> 1) * 8 + rr) * 128u;
    const uint32_t colSelB = (uint32_t)(quad & 1) * 16u;

    float c[4][4][4];
    #pragma unroll
    for (int mt = 0; mt < 4; mt++)
        #pragma unroll
        for (int nt = 0; nt < 4; nt++)
            #pragma unroll
            for (int r = 0; r < 4; r++) c[mt][nt][r] = 0.0f;

    auto issue = [&](int ch, int buf) {
        const uint32_t ba = sb + (uint32_t)buf * 32768u;
        const __half* qa = Aq + ch * 64;
        const __half* ka = Bk + ch * 64;
        #pragma unroll
        for (int i = 0; i < 4; i++) {
            cpasync16(ba + stsOff + i * 4096u,          qa + (size_t)i * 32 * 256);
            cpasync16(ba + 16384u + stsOff + i * 4096u, ka + (size_t)i * 32 * 256);
        }
        CP_COMMIT();
    };
    auto compute = [&](int buf) {
        const uint32_t aB = sb + (uint32_t)buf * 32768u + aRowOff;
        const uint32_t bB = sb + (uint32_t)buf * 32768u + 16384u + bRowOff;
        #pragma unroll
        for (int ks = 0; ks < 4; ks++) {
            const uint32_t ctA = ((uint32_t)(ks * 32) + colSelA) ^ swzL;
            const uint32_t ctB = ((uint32_t)(ks * 32) + colSelB) ^ swzL;
            uint32_t b[4][2];
            #pragma unroll
            for (int np = 0; np < 2; np++)
                ldm_x4(b[2*np][0], b[2*np][1], b[2*np+1][0], b[2*np+1][1],
                       bB + np * 2048u + ctB);
            #pragma unroll
            for (int mt = 0; mt < 4; mt++) {
                uint32_t a0, a1, a2, a3;
                ldm_x4(a0, a1, a2, a3, aB + mt * 2048u + ctA);
                #pragma unroll
                for (int nt = 0; nt < 4; nt++)
                    mma_f16f32(c[mt][nt], a0, a1, a2, a3, b[nt][0], b[nt][1]);
            }
        }
    };

    issue(0, 0); issue(1, 1);
    #pragma unroll 1
    for (int ch = 0; ch < 4; ch++) {
        if (ch == 3) { CP_WAIT(0); } else { CP_WAIT(1); }
        __syncthreads();
        compute(ch & 1);
        __syncthreads();
        if (ch + 2 < 4) issue(ch + 2, ch & 1);
    }

    #pragma unroll
    for (int mt = 0; mt < 4; mt++) {
        const int row = r0 + wm + mt * 16 + g;
        #pragma unroll
        for (int nt = 0; nt < 4; nt++) {
            const int col = h0 + wn + nt * 8 + 2 * t;
            float2 bc = *reinterpret_cast<const float2*>(&bias[col]);
            *reinterpret_cast<__half2*>(&outh[(size_t)row       * Hh + col]) =
                __floats2half2_rn(c[mt][nt][0] + bc.x, c[mt][nt][1] + bc.y);
            *reinterpret_cast<__half2*>(&outh[(size_t)(row + 8) * Hh + col]) =
                __floats2half2_rn(c[mt][nt][2] + bc.x, c[mt][nt][3] + bc.y);
        }
    }
}

// ---------------- kernel 3: P^T = exp(K Q^T * scale), Z sums, fp8 store ----------------
// Transposed scores: A = K-tile (128 k), B = Q-tile (256 q). Warp tile 64k x 64q.
// D fragments are q-adjacent -> e4m3x2 pack + STS.16 gives P^T[k][q] directly.
// grid: (N/256 q-tiles, N/128 k-tiles, B)  block: 256
__global__ __launch_bounds__(256, 2) void scores_fused_kernel() {
    extern __shared__ float dynsm[];
    __shared__ float rsum[256];
    const uint32_t sb = smem_u32(dynsm);
    const int tid  = threadIdx.x;
    const int wid  = tid >> 5;
    const int lane = tid & 31;
    const int g = lane >> 2, t = lane & 3;
    const int wm = (wid & 1) * 64;          // k offset
    const int wn = (wid >> 1) * 64;         // q offset
    const int lr = tid >> 3;
    const int lc = tid & 7;

    const int b  = blockIdx.z;
    const int q0 = blockIdx.x * 256;
    const int k0 = blockIdx.y * 128;

    const uint32_t stsOff = SW128((uint32_t)(lr * 128 + lc * 16));
    const __half* Aq = g_Kh + (size_t)(b * Nn + k0) * Hh + (size_t)lr * 256 + lc * 8;  // A = K
    const __half* Bk = g_Qh + (size_t)(b * Nn + q0) * Hh + (size_t)lr * 256 + lc * 8;  // B = Q

    const int quad = lane >> 3, rr = lane & 7;
    const uint32_t swzL = (uint32_t)rr << 4;
    const uint32_t aRowOff = (uint32_t)(wm + (quad & 1) * 8 + rr) * 128u;
    const uint32_t colSelA = (uint32_t)(quad >> 1) * 16u;
    const uint32_t bRowOff = (uint32_t)(wn + (quad >> 1) * 8 + rr) * 128u;
    const uint32_t colSelB = (uint32_t)(quad & 1) * 16u;

    uint32_t c[4][8][2];
    #pragma unroll
    for (int mt = 0; mt < 4; mt++)
        #pragma unroll
        for (int nt = 0; nt < 8; nt++) { c[mt][nt][0] = 0u; c[mt][nt][1] = 0u; }

    auto issue = [&](int ch, int buf) {
        const uint32_t ba = sb + (uint32_t)buf * 49152u;
        const __half* qa = Aq + ch * 64;
        const __half* ka = Bk + ch * 64;
        #pragma unroll
        for (int i = 0; i < 4; i++)
            cpasync16(ba + stsOff + i * 4096u, qa + (size_t)i * 32 * 256);
        #pragma unroll
        for (int i = 0; i < 8; i++)
            cpasync16(ba + 16384u + stsOff + i * 4096u, ka + (size_t)i * 32 * 256);
        CP_COMMIT();
    };
    auto compute = [&](int buf) {
        const uint32_t aB = sb + (uint32_t)buf * 49152u + aRowOff;
        const uint32_t bB = sb + (uint32_t)buf * 49152u + 16384u + bRowOff;
        #pragma unroll
        for (int ks = 0; ks < 4; ks++) {
            const uint32_t ctA = ((uint32_t)(ks * 32) + colSelA) ^ swzL;
            const uint32_t ctB = ((uint32_t)(ks * 32) + colSelB) ^ swzL;
            uint32_t b[8][2];
            #pragma unroll
            for (int np = 0; np < 4; np++)
                ldm_x4(b[2*np][0], b[2*np][1], b[2*np+1][0], b[2*np+1][1],
                       bB + np * 2048u + ctB);
            #pragma unroll
            for (int mt = 0; mt < 4; mt++) {
                uint32_t a0, a1, a2, a3;
                ldm_x4(a0, a1, a2, a3, aB + mt * 2048u + ctA);
                #pragma unroll
                for (int nt = 0; nt < 8; nt++)
                    mma_f16(c[mt][nt], a0, a1, a2, a3, b[nt][0], b[nt][1]);
            }
        }
    };

    issue(0, 0); issue(1, 1);
    #pragma unroll 1
    for (int ch = 0; ch < 4; ch++) {
        if (ch == 3) { CP_WAIT(0); } else { CP_WAIT(1); }
        __syncthreads();
        compute(ch & 1);
        __syncthreads();
        if (ch + 2 < 4) issue(ch + 2, ch & 1);
    }

    // ---- epilogue 1: exp, e4m3 pack into P^T smem stage, Z partials ----
    rsum[tid] = 0.0f;
    __syncthreads();

    const __half2 scale2 = __float2half2_rn(0.0625f);
    __half2 zn[8];
    #pragma unroll
    for (int nt = 0; nt < 8; nt++) zn[nt] = __float2half2_rn(0.0f);

    #pragma unroll
    for (int mt = 0; mt < 4; mt++) {
        const int row = wm + mt * 16 + g;        // k row (CTA-local)
        #pragma unroll
        for (int nt = 0; nt < 8; nt++) {
            const uint32_t qb = (uint32_t)(wn + nt * 8 + 2 * t);   // q byte offset
            __half2 c0 = *reinterpret_cast<__half2*>(&c[mt][nt][0]);
            __half2 c1 = *reinterpret_cast<__half2*>(&c[mt][nt][1]);
            __half2 e0 = h2exp(__hmul2(c0, scale2));
            __half2 e1 = h2exp(__hmul2(c1, scale2));
            sts16(sb + (uint32_t)row       * PT_STRIDE + qb, h2_to_e4m3x2(*(uint32_t*)&e0));
            sts16(sb + (uint32_t)(row + 8) * PT_STRIDE + qb, h2_to_e4m3x2(*(uint32_t*)&e1));
            zn[nt] = __hadd2(zn[nt], __hadd2(e0, e1));
        }
    }
    #pragma unroll
    for (int nt = 0; nt < 8; nt++) {
        // reduce over g (lane bits 2,3,4)
        uint32_t u = *(uint32_t*)&zn[nt];
        #pragma unroll
        for (int m = 4; m <= 16; m <<= 1) {
            uint32_t o = __shfl_xor_sync(0xFFFFFFFFu, u, m);
            __half2 a = *(__half2*)&u, bb = *(__half2*)&o;
            __half2 s = __hadd2(a, bb);
            u = *(uint32_t*)&s;
        }
        if (lane < 4) {
            float2 f = __half22float2(*(__half2*)&u);
            atomicAdd(&rsum[wn + nt * 8 + 2 * lane],     f.x);
            atomicAdd(&rsum[wn + nt * 8 + 2 * lane + 1], f.y);
        }
    }
    __syncthreads();

    // ---- epilogue 2: coalesced fp8 write-out of P^T, Z flush ----
    const char* Ps = reinterpret_cast<const char*>(dynsm);
    #pragma unroll 4
    for (int i = tid; i < 128 * 16; i += 256) {
        const int row = i >> 4;
        const int u4  = i & 15;
        uint4 v = *reinterpret_cast<const uint4*>(Ps + row * PT_STRIDE + u4 * 16);
        *reinterpret_cast<uint4*>(&g_P8[((size_t)(b * Nn + k0 + row)) * Nn + q0 + u4 * 16]) = v;
    }
    atomicAdd(&g_z[b * Nn + q0 + tid], rsum[tid]);
}

// ---------------- kernel 4: c' = 4096/Z split into two e4m3 levels ----------------
__global__ __launch_bounds__(256) void cprep_kernel() {
    int q = blockIdx.x * 256 + threadIdx.x;
    float cp = 4096.0f / g_z[q];
    uint16_t hp;
    asm("cvt.rn.satfinite.e4m3x2.f32 %0, %1, %2;" : "=h"(hp) : "f"(0.0f), "f"(cp));
    uint32_t hdec;
    asm("cvt.rn.f16x2.e4m3x2 %0, %1;" : "=r"(hdec) : "h"(hp));
    float hif = __half2float(*reinterpret_cast<__half*>(&hdec));
    float r = (cp - hif) * 32.0f;
    uint16_t lp;
    asm("cvt.rn.satfinite.e4m3x2.f32 %0, %1, %2;" : "=h"(lp) : "f"(0.0f), "f"(r));
    g_chi[q] = (uint8_t)(hp & 0xFF);
    g_clo[q] = (uint8_t)(lp & 0xFF);
}

// ---------------- kernel 5: w = c'^T @ P^T via fp8 MMA ----------------
// CTA: 64 k-rows x full q=4096 (chunks of 64). A rows 0/1 = c_hi/c_lo, rows 2-15 zero.
// grid: (N/64, B)  block: 256 (8 warps x 8 k each)
__global__ __launch_bounds__(256) void colsum_kernel() {
    __shared__ uint8_t chs[4096], cls[4096];
    __shared__ uint8_t ptile[2][64 * 144];
    const int tid  = threadIdx.x;
    const int wid  = tid >> 5;
    const int lane = tid & 31;
    const int jr = lane >> 2, tc = lane & 3;
    const int b  = blockIdx.y;
    const int k0 = blockIdx.x * 64;

    const uint32_t chs_a = smem_u32(chs), cls_a = smem_u32(cls);
    const uint32_t pt_a[2] = { smem_u32(ptile[0]), smem_u32(ptile[1]) };

    auto issue = [&](int ch, int buf) {
        const int row = tid >> 2, piece = tid & 3;
        cpasync16(pt_a[buf] + (uint32_t)(row * 144 + piece * 16),
                  g_P8 + ((size_t)(b * Nn + k0 + row)) * Nn + ch * 64 + piece * 16);
        CP_COMMIT();
    };

    // c stage (16 B per thread each) goes in the first commit group
    cpasync16(chs_a + tid * 16, g_chi + b * Nn + tid * 16);
    cpasync16(cls_a + tid * 16, g_clo + b * Nn + tid * 16);
    issue(0, 0);
    issue(1, 1);

    float d[4] = {0.0f, 0.0f, 0.0f, 0.0f};

    #pragma unroll 1
    for (int ch = 0; ch < 64; ch++) {
        if (ch == 63) { CP_WAIT(0); } else { CP_WAIT(1); }
        __syncthreads();
        const uint32_t tb = pt_a[ch & 1] + (uint32_t)((wid * 8 + jr) * 144);
        #pragma unroll
        for (int ks = 0; ks < 2; ks++) {
            const int qb = ch * 64 + ks * 32;
            uint32_t a0 = 0, a2 = 0;
            if (jr == 0) {
                a0 = *reinterpret_cast<const uint32_t*>(&chs[qb + tc * 4]);
                a2 = *reinterpret_cast<const uint32_t*>(&chs[qb + tc * 4 + 16]);
            } else if (jr == 1) {
                a0 = *reinterpret_cast<const uint32_t*>(&cls[qb + tc * 4]);
                a2 = *reinterpret_cast<const uint32_t*>(&cls[qb + tc * 4 + 16]);
            }
            uint32_t b0, b1;
            asm volatile("ld.shared.b32 %0, [%1];" : "=r"(b0) : "r"(tb + ks * 32 + tc * 4));
            asm volatile("ld.shared.b32 %0, [%1];" : "=r"(b1) : "r"(tb + ks * 32 + tc * 4 + 16));
            mma_fp8(d, a0, 0u, a2, 0u, b0, b1);
        }
        __syncthreads();
        if (ch + 2 < 64) issue(ch + 2, ch & 1);
    }

    // combine hi/lo: lane l<4 holds hi (row0) for cols 2l,2l+1; lane l+4 holds lo (row1)
    float lo0 = __shfl_down_sync(0xFFFFFFFFu, d[0], 4);
    float lo1 = __shfl_down_sync(0xFFFFFFFFu, d[1], 4);
    if (lane < 4) {
        g_w[b * Nn + k0 + wid * 8 + 2 * lane]     = d[0] + lo0 * (1.0f / 32.0f);
        g_w[b * Nn + k0 + wid * 8 + 2 * lane + 1] = d[1] + lo1 * (1.0f / 32.0f);
    }
}

// ---------------- kernel 6: out[b,h] = sum_k w[b,k] V[b,k,h] / (N*4096) ----------------
__global__ __launch_bounds__(256) void out_kernel(float* __restrict__ out) {
    const int b  = blockIdx.x;
    const int ks = blockIdx.y;
    const int h  = threadIdx.x;
    const __half* Vb = g_Vh + (size_t)b * Nn * Hh;

    float acc = 0.0f;
    #pragma unroll 8
    for (int k = ks * 256; k < ks * 256 + 256; k++)
        acc += g_w[b * Nn + k] * __half2float(Vb[(size_t)k * Hh + h]);

    atomicAdd(&out[b * Hh + h], acc * (1.0f / 16777216.0f));
}

// ---------------- launch ----------------
extern "C" void kernel_launch(void* const* d_in, const int* in_sizes, int n_in,
                              void* d_out, int out_size) {
    const float* x  = (const float*)d_in[0];
    const float* Wq = (const float*)d_in[1];
    const float* bq = (const float*)d_in[2];
    const float* Wk = (const float*)d_in[3];
    const float* bk = (const float*)d_in[4];
    const float* Wv = (const float*)d_in[5];
    const float* bv = (const float*)d_in[6];
    float* out = (float*)d_out;

    cudaFuncSetAttribute(qkv_mma_kernel,
                         cudaFuncAttributeMaxDynamicSharedMemorySize, QKV_DYN_SMEM);
    cudaFuncSetAttribute(scores_fused_kernel,
                         cudaFuncAttributeMaxDynamicSharedMemorySize, SC_DYN_SMEM);

    convert_x_kernel<<<(Bb * Nn * Dd / 2) / 256, 256>>>(x, out);
    transpose_w_kernel<<<dim3(8, 8, 3), dim3(32, 8)>>>(Wq, Wk, Wv);
    qkv_mma_kernel<<<dim3(Hh / 128, (Bb * Nn) / 128, 3), 256, QKV_DYN_SMEM>>>(bq, bk, bv);
    scores_fused_kernel<<<dim3(Nn / 256, Nn / 128, Bb), 256, SC_DYN_SMEM>>>();
    cprep_kernel<<<(Bb * Nn) / 256, 256>>>();
    colsum_kernel<<<dim3(Nn / 64, Bb), 256>>>();
    out_kernel<<<dim3(Bb, 16), 256>>>(out);
}